// round 1
// baseline (speedup 1.0000x reference)
#include <cuda_runtime.h>

// Problem constants (fixed by setup_inputs)
#define BB   8
#define SS   1024
#define MM   8
#define SMEM_TOK 1032          // S + M
#define DD   768
#define HH   12
#define DH   64
#define NROWS (BB * SMEM_TOK)  // 8256 = 129 * 64

// Scratch: Q/K/V in (B, H, S+M, Dh) layout, fp32
__device__ float g_Q[BB * HH * SMEM_TOK * DH];
__device__ float g_K[BB * HH * SMEM_TOK * DH];
__device__ float g_V[BB * HH * SMEM_TOK * DH];

// ---------------------------------------------------------------------------
// Kernel 1: fused QKV projection.  out = X @ W^T + b
// X rows: concat(hidden, memory) per batch (gathered on the fly).
// grid = (129, 12, 3): 129 row tiles of 64, 12 col tiles of 64 (== one head),
// z selects Q/K/V. 256 threads, 4x4 micro-tile, BK=16.
// ---------------------------------------------------------------------------
__global__ __launch_bounds__(256) void qkv_gemm(
    const float* __restrict__ hid, const float* __restrict__ mem,
    const float* __restrict__ Wq, const float* __restrict__ bq,
    const float* __restrict__ Wk, const float* __restrict__ bk,
    const float* __restrict__ Wv, const float* __restrict__ bv)
{
    const int mtile = blockIdx.x;          // row tile (64 rows)
    const int h     = blockIdx.y;          // head == 64-col tile
    const int which = blockIdx.z;          // 0=Q 1=K 2=V

    const float* W    = (which == 0) ? Wq : (which == 1) ? Wk : Wv;
    const float* bias = (which == 0) ? bq : (which == 1) ? bk : bv;
    float* Obuf       = (which == 0) ? g_Q : (which == 1) ? g_K : g_V;

    __shared__ float As[16][64];   // [k][m]
    __shared__ float Bs[16][64];   // [k][n]

    const int tid = threadIdx.x;
    const int tm = (tid >> 4) * 4;         // 0..60
    const int tn = (tid & 15) * 4;         // 0..60

    // loader mapping: 64 rows x 16 k, float4 per thread
    const int la_r = tid >> 2;             // 0..63 (row within tile)
    const int la_c = (tid & 3) * 4;        // k offset: 0,4,8,12

    const int row0 = mtile * 64;
    const int grow = row0 + la_r;          // global token row, < 8256 always
    const int gb = grow / SMEM_TOK;
    const int gs = grow % SMEM_TOK;
    const float* arow = (gs < SS) ? (hid + (gb * SS + gs) * DD)
                                  : (mem + (gs - SS) * DD);
    const float* brow = W + (h * 64 + la_r) * DD;

    float acc[4][4] = {};

    for (int kk = 0; kk < DD; kk += 16) {
        float4 av = *(const float4*)(arow + kk + la_c);
        float4 bv4 = *(const float4*)(brow + kk + la_c);
        As[la_c + 0][la_r] = av.x;  As[la_c + 1][la_r] = av.y;
        As[la_c + 2][la_r] = av.z;  As[la_c + 3][la_r] = av.w;
        Bs[la_c + 0][la_r] = bv4.x; Bs[la_c + 1][la_r] = bv4.y;
        Bs[la_c + 2][la_r] = bv4.z; Bs[la_c + 3][la_r] = bv4.w;
        __syncthreads();
        #pragma unroll
        for (int k = 0; k < 16; k++) {
            float a[4], b[4];
            *(float4*)a = *(const float4*)&As[k][tm];
            *(float4*)b = *(const float4*)&Bs[k][tn];
            #pragma unroll
            for (int i = 0; i < 4; i++)
                #pragma unroll
                for (int j = 0; j < 4; j++)
                    acc[i][j] += a[i] * b[j];
        }
        __syncthreads();
    }

    #pragma unroll
    for (int i = 0; i < 4; i++) {
        const int gr = row0 + tm + i;
        const int ob = gr / SMEM_TOK;
        const int os = gr % SMEM_TOK;
        float* orow = Obuf + ((ob * HH + h) * SMEM_TOK + os) * DH;
        #pragma unroll
        for (int j = 0; j < 4; j++)
            orow[tn + j] = acc[i][j] + bias[h * 64 + tn + j];
    }
}

// ---------------------------------------------------------------------------
// Kernel 2: attention. One query row per thread, 128 threads/block.
// K/V tiles of 64 keys in shared (broadcast float4 reads), online softmax.
// grid = 768 (= B*H * S/128)
// ---------------------------------------------------------------------------
__global__ __launch_bounds__(128) void attn(float* __restrict__ out)
{
    const int bid  = blockIdx.x;
    const int qblk = bid & 7;              // S/128 = 8 blocks per (b,h)
    const int bh   = bid >> 3;             // 0..95
    const int b    = bh / HH;
    const int h    = bh % HH;
    const int q    = qblk * 128 + threadIdx.x;   // query position (< 1024)

    const float* Qrow = g_Q + ((b * HH + h) * SMEM_TOK + q) * DH;
    const float* Kbase = g_K + (b * HH + h) * SMEM_TOK * DH;
    const float* Vbase = g_V + (b * HH + h) * SMEM_TOK * DH;

    float qr[DH];
    #pragma unroll
    for (int d = 0; d < DH; d++) qr[d] = Qrow[d] * 0.125f;  // 1/sqrt(64)

    float o[DH];
    #pragma unroll
    for (int d = 0; d < DH; d++) o[d] = 0.f;
    float mmax = -1e30f, l = 0.f;

    __shared__ float Ks[64][64];
    __shared__ float Vs[64][64];

    for (int kt = 0; kt < SMEM_TOK; kt += 64) {
        const int tsz = min(64, SMEM_TOK - kt);   // 64 or 8 (last tile)
        __syncthreads();
        for (int i = threadIdx.x; i < tsz * 16; i += 128) {
            const int r = i >> 4, c4 = (i & 15) * 4;
            *(float4*)&Ks[r][c4] = *(const float4*)(Kbase + (kt + r) * DH + c4);
            *(float4*)&Vs[r][c4] = *(const float4*)(Vbase + (kt + r) * DH + c4);
        }
        __syncthreads();

        for (int c0 = 0; c0 < tsz; c0 += 16) {
            float sc[16];
            float tmax = mmax;
            #pragma unroll
            for (int k = 0; k < 16; k++) {
                if (c0 + k < tsz) {
                    float s = 0.f;
                    #pragma unroll
                    for (int d4 = 0; d4 < 16; d4++) {
                        float4 kv = *(const float4*)&Ks[c0 + k][d4 * 4];
                        s += qr[d4*4+0] * kv.x + qr[d4*4+1] * kv.y
                           + qr[d4*4+2] * kv.z + qr[d4*4+3] * kv.w;
                    }
                    sc[k] = s;
                    tmax = fmaxf(tmax, s);
                } else {
                    sc[k] = -1e30f;
                }
            }
            const float alpha = __expf(mmax - tmax);
            mmax = tmax;
            l *= alpha;
            #pragma unroll
            for (int d = 0; d < DH; d++) o[d] *= alpha;
            #pragma unroll
            for (int k = 0; k < 16; k++) {
                const float p = __expf(sc[k] - mmax);
                l += p;
                #pragma unroll
                for (int d4 = 0; d4 < 16; d4++) {
                    float4 vv = *(const float4*)&Vs[c0 + k][d4 * 4];
                    o[d4*4+0] += p * vv.x;  o[d4*4+1] += p * vv.y;
                    o[d4*4+2] += p * vv.z;  o[d4*4+3] += p * vv.w;
                }
            }
        }
    }

    const float inv = 1.f / l;
    float* orow = out + (b * SS + q) * DD + h * DH;
    #pragma unroll
    for (int d = 0; d < DH; d++) orow[d] = o[d] * inv;
}

// ---------------------------------------------------------------------------
extern "C" void kernel_launch(void* const* d_in, const int* in_sizes, int n_in,
                              void* d_out, int out_size)
{
    const float* hid = (const float*)d_in[0];
    const float* mem = (const float*)d_in[1];
    const float* Wq  = (const float*)d_in[2];
    const float* bq  = (const float*)d_in[3];
    const float* Wk  = (const float*)d_in[4];
    const float* bk  = (const float*)d_in[5];
    const float* Wv  = (const float*)d_in[6];
    const float* bv  = (const float*)d_in[7];

    dim3 g1(NROWS / 64, HH, 3);            // (129, 12, 3)
    qkv_gemm<<<g1, 256>>>(hid, mem, Wq, bq, Wk, bk, Wv, bv);

    attn<<<(BB * HH * SS) / 128, 128>>>((float*)d_out);
}